// round 1
// baseline (speedup 1.0000x reference)
#include <cuda_runtime.h>
#include <stdint.h>

#define BATCH 32768
#define DIM   256
#define NF    4096
#define TOPK  32

// Scratch (no allocs allowed): normalized/centered input + transposed decoder.
static __device__ float g_xc[BATCH * DIM];        // 33.5 MB
static __device__ float g_WdecT[NF * DIM];        // 4 MB

// ---------------------------------------------------------------------------
// Prep: xc = (x - mean)/std - b_dec   (fp32-exact, done once so the GEMM
// doesn't redo 3 flops + a division per A-element per N-tile)
// ---------------------------------------------------------------------------
__global__ void __launch_bounds__(256) prep_xc_kernel(
    const float* __restrict__ x,
    const float* __restrict__ mean,
    const float* __restrict__ stdv,
    const float* __restrict__ bdec)
{
    int idx = blockIdx.x * blockDim.x + threadIdx.x;   // float4 index
    int col4 = (idx * 4) & (DIM - 1);
    float4 xv = ((const float4*)x)[idx];
    float4 m = *(const float4*)(mean + col4);
    float4 s = *(const float4*)(stdv + col4);
    float4 b = *(const float4*)(bdec + col4);
    float4 r;
    r.x = (xv.x - m.x) / s.x - b.x;
    r.y = (xv.y - m.y) / s.y - b.y;
    r.z = (xv.z - m.z) / s.z - b.z;
    r.w = (xv.w - m.w) / s.w - b.w;
    ((float4*)g_xc)[idx] = r;
}

// ---------------------------------------------------------------------------
// Transpose W_dec (D,N) -> W_decT (N,D) so decode gathers whole coalesced rows.
// ---------------------------------------------------------------------------
__global__ void transpose_wdec(const float* __restrict__ Wdec)
{
    __shared__ float tile[32][33];
    int n = blockIdx.x * 32 + threadIdx.x;
    int d = blockIdx.y * 32 + threadIdx.y;
    tile[threadIdx.y][threadIdx.x] = Wdec[(size_t)d * NF + n];
    __syncthreads();
    int n2 = blockIdx.x * 32 + threadIdx.y;
    int d2 = blockIdx.y * 32 + threadIdx.x;
    g_WdecT[(size_t)n2 * DIM + d2] = tile[threadIdx.x][threadIdx.y];
}

// ---------------------------------------------------------------------------
// Encode GEMM: h_pre[b,n] = sum_d xc[b,d] * W_enc[n,d] + b_enc[n]
// fp32 SIMT, BM=BN=128, BK=8, 256 threads, 8x8 per thread.
// ---------------------------------------------------------------------------
#define BM 128
#define BN 128
#define BK 8

__global__ void __launch_bounds__(256) sgemm_kernel(
    const float* __restrict__ Wenc,
    const float* __restrict__ benc,
    float* __restrict__ hpre)
{
    __shared__ float As[BK][BM + 4];
    __shared__ float Bs[BK][BN + 4];

    const int tid = threadIdx.x;
    const int tx = tid & 15;
    const int ty = tid >> 4;
    const int lr = tid >> 1;          // 0..127
    const int lc = (tid & 1) * 4;     // 0 or 4

    const float* Ap = g_xc + (size_t)(blockIdx.y * BM + lr) * DIM + lc;
    const float* Bp = Wenc + (size_t)(blockIdx.x * BN + lr) * DIM + lc;

    float acc[8][8];
#pragma unroll
    for (int i = 0; i < 8; i++)
#pragma unroll
        for (int j = 0; j < 8; j++) acc[i][j] = 0.f;

    for (int k0 = 0; k0 < DIM; k0 += BK) {
        float4 a4 = *(const float4*)(Ap + k0);
        float4 b4 = *(const float4*)(Bp + k0);
        As[lc + 0][lr] = a4.x;
        As[lc + 1][lr] = a4.y;
        As[lc + 2][lr] = a4.z;
        As[lc + 3][lr] = a4.w;
        Bs[lc + 0][lr] = b4.x;
        Bs[lc + 1][lr] = b4.y;
        Bs[lc + 2][lr] = b4.z;
        Bs[lc + 3][lr] = b4.w;
        __syncthreads();
#pragma unroll
        for (int kk = 0; kk < BK; kk++) {
            float ar[8], br[8];
            *(float4*)&ar[0] = *(const float4*)&As[kk][ty * 8];
            *(float4*)&ar[4] = *(const float4*)&As[kk][ty * 8 + 4];
            *(float4*)&br[0] = *(const float4*)&Bs[kk][tx * 8];
            *(float4*)&br[4] = *(const float4*)&Bs[kk][tx * 8 + 4];
#pragma unroll
            for (int i = 0; i < 8; i++)
#pragma unroll
                for (int j = 0; j < 8; j++)
                    acc[i][j] += ar[i] * br[j];
        }
        __syncthreads();
    }

    const int crow0 = blockIdx.y * BM + ty * 8;
    const int ccol0 = blockIdx.x * BN + tx * 8;
    float4 be0 = *(const float4*)(benc + ccol0);
    float4 be1 = *(const float4*)(benc + ccol0 + 4);
#pragma unroll
    for (int i = 0; i < 8; i++) {
        float4 o0, o1;
        o0.x = acc[i][0] + be0.x; o0.y = acc[i][1] + be0.y;
        o0.z = acc[i][2] + be0.z; o0.w = acc[i][3] + be0.w;
        o1.x = acc[i][4] + be1.x; o1.y = acc[i][5] + be1.y;
        o1.z = acc[i][6] + be1.z; o1.w = acc[i][7] + be1.w;
        float* cp = hpre + (size_t)(crow0 + i) * NF + ccol0;
        *(float4*)cp = o0;
        *(float4*)(cp + 4) = o1;
    }
}

// ---------------------------------------------------------------------------
// Fused top-K (exact 4-pass radix select on monotonic uint keys) + scatter
// into h_sparse + sparse decode.  One 256-thread block per row; the 4096
// values live in registers (16/thread).
// ---------------------------------------------------------------------------
__global__ void __launch_bounds__(256) topk_decode_kernel(
    const float* __restrict__ hpre,
    const float* __restrict__ bdec,
    float* __restrict__ hsp,
    float* __restrict__ xhat)
{
    __shared__ unsigned hist[256];
    __shared__ unsigned ssum[256];
    __shared__ unsigned sh_byte, sh_excl;
    __shared__ int sh_ngt, sh_neq;
    __shared__ int   sidx[TOPK];
    __shared__ float sval[TOPK];

    const int row = blockIdx.x;
    const int tid = threadIdx.x;
    const float* rp = hpre + (size_t)row * NF;

    float v[16];
    unsigned key[16];
#pragma unroll
    for (int i = 0; i < 16; i++) {
        v[i] = rp[tid + 256 * i];
        unsigned u = __float_as_uint(v[i]);
        key[i] = (u & 0x80000000u) ? ~u : (u | 0x80000000u);  // order-preserving
    }

    unsigned prefix = 0;
    unsigned rem = TOPK;
#pragma unroll
    for (int byte = 3; byte >= 0; byte--) {
        hist[tid] = 0;
        __syncthreads();
        const int sh = byte * 8;
#pragma unroll
        for (int i = 0; i < 16; i++) {
            bool match = (byte == 3) || ((key[i] >> (sh + 8)) == prefix);
            if (match) atomicAdd(&hist[(key[i] >> sh) & 255u], 1u);
        }
        __syncthreads();
        ssum[tid] = hist[tid];
        __syncthreads();
        // suffix (from-the-top) inclusive scan over 256 bins
#pragma unroll
        for (int off = 1; off < 256; off <<= 1) {
            unsigned add = (tid + off < 256) ? ssum[tid + off] : 0u;
            __syncthreads();
            ssum[tid] += add;
            __syncthreads();
        }
        unsigned incl = ssum[tid];
        unsigned excl = incl - hist[tid];
        if (excl < rem && incl >= rem) { sh_byte = (unsigned)tid; sh_excl = excl; }
        __syncthreads();
        prefix = (prefix << 8) | sh_byte;
        rem -= sh_excl;
        __syncthreads();
    }
    const unsigned T = prefix;  // exact 32-bit key of the K-th largest value

    if (tid == 0) { sh_ngt = 0; sh_neq = 0; }
    __syncthreads();

    float* hrow = hsp + (size_t)row * NF;
#pragma unroll
    for (int i = 0; i < 16; i++) {
        if (key[i] > T) {
            int p = atomicAdd(&sh_ngt, 1);
            int col = tid + 256 * i;
            sidx[p] = col; sval[p] = v[i];
            hrow[col] = v[i];
        }
    }
    __syncthreads();
    const int base = sh_ngt;   // == TOPK - rem
#pragma unroll
    for (int i = 0; i < 16; i++) {
        if (key[i] == T) {
            int q = atomicAdd(&sh_neq, 1);
            if (q < (int)rem) {                 // take exactly 'rem' ties
                int col = tid + 256 * i;
                sidx[base + q] = col; sval[base + q] = v[i];
                hrow[col] = v[i];
            }
        }
    }
    __syncthreads();

    // Sparse decode: x_hat[row,d] = b_dec[d] + sum_j sval[j]*W_decT[sidx[j],d]
    float acc = bdec[tid];
#pragma unroll
    for (int j = 0; j < TOPK; j++)
        acc += sval[j] * g_WdecT[(size_t)sidx[j] * DIM + tid];
    xhat[(size_t)row * DIM + tid] = acc;
}

// ---------------------------------------------------------------------------
extern "C" void kernel_launch(void* const* d_in, const int* in_sizes, int n_in,
                              void* d_out, int out_size)
{
    const float* x    = (const float*)d_in[0];
    const float* Wenc = (const float*)d_in[1];
    const float* benc = (const float*)d_in[2];
    const float* Wdec = (const float*)d_in[3];
    const float* bdec = (const float*)d_in[4];
    const float* mean = (const float*)d_in[5];
    const float* stdv = (const float*)d_in[6];

    float* out  = (float*)d_out;
    float* xhat = out;                               // (B, D)
    float* hsp  = out + (size_t)BATCH * DIM;         // (B, N)
    float* hpre = hsp + (size_t)BATCH * NF;          // (B, N)

    // h_sparse is mostly zeros: bulk-zero it, then scatter the K live values.
    cudaMemsetAsync(hsp, 0, (size_t)BATCH * NF * sizeof(float), 0);

    prep_xc_kernel<<<(BATCH * DIM / 4) / 256, 256>>>(x, mean, stdv, bdec);

    dim3 tb(32, 32);
    dim3 tg(NF / 32, DIM / 32);
    transpose_wdec<<<tg, tb>>>(Wdec);

    dim3 gg(NF / BN, BATCH / BM);
    sgemm_kernel<<<gg, 256>>>(Wenc, benc, hpre);

    topk_decode_kernel<<<BATCH, 256>>>(hpre, bdec, hsp, xhat);
}